// round 6
// baseline (speedup 1.0000x reference)
#include <cuda_runtime.h>
#include <cuda_fp16.h>
#include <math.h>
#include <stdint.h>

// ================= problem constants =================
#define MCAP   100096              // 782*128 padded row capacity
#define K1     1152
#define HIDN   1024
#define ODIMN  512

// ================= scratch (device globals; allocation-free rule) =================
__device__ __half g_x1h[(size_t)MCAP * K1];     // x1, half, row-major, permuted cols
__device__ __half g_hh [(size_t)MCAP * HIDN];   // h,  half, row-major
__device__ float  g_y  [(size_t)MCAP * ODIMN];  // y,  fp32, row-major
__device__ __half g_w1t[(size_t)HIDN * K1];     // W1^T [N][K], permuted rows
__device__ __half g_w2t[(size_t)ODIMN * HIDN];  // W2^T [N][K]

// ================= helpers =================
__device__ __forceinline__ uint32_t smem_u32(const void* p) {
    uint32_t a;
    asm("{ .reg .u64 t; cvta.to.shared.u64 t, %1; cvt.u32.u64 %0, t; }" : "=r"(a) : "l"(p));
    return a;
}
// XOR swizzle: 16B chunk (bits 4-6) ^ row%8 (bits 7-9); rows are 128B
__device__ __forceinline__ uint32_t swz(uint32_t b) { return b ^ ((b >> 3) & 0x70); }

__device__ __forceinline__ void cpa16(uint32_t dst, const void* src) {
    asm volatile("cp.async.cg.shared.global [%0], [%1], 16;" :: "r"(dst), "l"(src) : "memory");
}
#define CP_COMMIT() asm volatile("cp.async.commit_group;" ::: "memory")
#define CP_WAIT(n)  asm volatile("cp.async.wait_group %0;" :: "n"(n) : "memory")

// ================= prep: x1 (half, permuted cols, padded rows zeroed) =================
// col order: [x0(128) | vl_j0(128) | vl_j1(128) | vl_j2(128) | norm(128) | extra(512)]
__global__ void prep_kernel(const float* __restrict__ x, const float* __restrict__ rot,
                            const float* __restrict__ extra, int Mreal) {
    int n = blockIdx.x, f = threadIdx.x;
    bool real = n < Mreal;
    __shared__ float R[9];
    if (real && f < 9) R[f] = rot[(size_t)n * 9 + f];
    __syncthreads();

    float x0 = 0.f, v1 = 0.f, v2 = 0.f, v3 = 0.f;
    if (real) {
        const float* xr = x + (size_t)n * 512;
        x0 = xr[f]; v1 = xr[128 + f]; v2 = xr[256 + f]; v3 = xr[384 + f];
    }
    __half* o = g_x1h + (size_t)n * K1;
    o[f] = __float2half(x0);
#pragma unroll
    for (int j = 0; j < 3; ++j) {
        float vl = real ? (v1 * R[j] + v2 * R[3 + j] + v3 * R[6 + j]) : 0.f;
        o[128 + 128 * j + f] = __float2half(vl);
    }
    o[512 + f] = __float2half(real ? sqrtf(v1 * v1 + v2 * v2 + v3 * v3 + 1e-4f) : 0.f);
#pragma unroll
    for (int j = 0; j < 4; ++j) {
        float e = real ? extra[(size_t)n * 512 + 128 * j + f] : 0.f;
        o[640 + 128 * j + f] = __float2half(e);
    }
}

// ================= weight prep: W[K][N] fp32 -> W^T[N][K] half (PERM row remap for W1) ======
template<int PERM>
__global__ void wprep_kernel(const float* __restrict__ W, __half* __restrict__ dst, int K, int N) {
    long t = (long)blockIdx.x * blockDim.x + threadIdx.x;
    if (t >= (long)N * K) return;
    int n = (int)(t / K), k = (int)(t % K);
    int nk = k;
    if (PERM && k >= 128 && k < 512) {
        int q = k - 128;
        nk = 128 + (q % 3) * 128 + (q / 3);
    }
    dst[(size_t)n * K + nk] = __float2half(W[(size_t)k * N + n]);
}

// ================= fp16 tensor-core GEMM =================
// C[M,ND] = A[M,KD] @ B^T (B stored [ND][KD] half).
// CTA tile 128x256x64, 256 thr = 8 warps (2x4), warp tile 64x64,
// mma.m16n8k16, all-x4 ldmatrix, frag double-buffer, 3-stage cp.async (1 sync/iter).
#define BKB   128                      // BK bytes per row (64 halfs)
#define STAGE 49152                    // 16KB A + 32KB B
#define SMEMB (3 * STAGE)              // 147456

template<int KD, int ND, int GELU>
__global__ void __launch_bounds__(256, 1)
gemm_h(const __half* __restrict__ A, const __half* __restrict__ B,
       const float* __restrict__ bias, void* __restrict__ outv, int Mreal) {
    extern __shared__ char smem[];
    const uint32_t sbase = smem_u32(smem);

    const int tid = threadIdx.x, lane = tid & 31;
    const int warp = tid >> 5;
    const int wm = (warp >> 2) * 64;         // warp row offset (0,64)
    const int wn = (warp & 3) * 64;          // warp col offset (0..192)
    const int g = lane >> 2, t4 = lane & 3;
    const size_t rowBase = (size_t)blockIdx.y * 128;
    const int colBase = blockIdx.x * 256;

    // ldmatrix lane address components
    const int aR = (lane & 7) + ((lane >> 3) & 1) * 8;   // A: row within m16
    const int aK = (lane >> 4) * 8;                      // A: k-half
    const int bR = lane & 7;                             // B: row within n8
    const int bJ = (lane >> 4) & 1;                      // B: j sub-block (x4 spans 2 n8s)
    const int bK = ((lane >> 3) & 1) * 8;                // B: k-half

    float acc[4][8][4];
#pragma unroll
    for (int i = 0; i < 4; ++i)
#pragma unroll
        for (int j = 0; j < 8; ++j)
#pragma unroll
            for (int r = 0; r < 4; ++r) acc[i][j][r] = 0.0f;

    auto loadTile = [&](int k0, int s) {
        const uint32_t sA = sbase + s * STAGE;
        const uint32_t sB = sA + 16384;
#pragma unroll
        for (int p = 0; p < 4; ++p) {                 // A: 1024 16B chunks
            int idx = tid + p * 256;
            int r = idx >> 3, c = idx & 7;
            cpa16(sA + swz((uint32_t)(r * BKB + c * 16)),
                  A + (rowBase + r) * KD + k0 + c * 8);
        }
#pragma unroll
        for (int p = 0; p < 8; ++p) {                 // B: 2048 16B chunks
            int idx = tid + p * 256;
            int r = idx >> 3, c = idx & 7;
            cpa16(sB + swz((uint32_t)(r * BKB + c * 16)),
                  B + (size_t)(colBase + r) * KD + k0 + c * 8);
        }
    };

    uint32_t af[2][4][4], bf[2][8][2];
    auto ldFrags = [&](int buf, int s, int kk) {
        const uint32_t sA = sbase + s * STAGE;
        const uint32_t sB = sA + 16384;
#pragma unroll
        for (int i = 0; i < 4; ++i) {
            uint32_t a = sA + swz((uint32_t)((wm + 16 * i + aR) * BKB + (kk + aK) * 2));
            asm volatile("ldmatrix.sync.aligned.m8n8.x4.shared.b16 {%0,%1,%2,%3}, [%4];"
                         : "=r"(af[buf][i][0]), "=r"(af[buf][i][1]),
                           "=r"(af[buf][i][2]), "=r"(af[buf][i][3]) : "r"(a));
        }
#pragma unroll
        for (int j0 = 0; j0 < 8; j0 += 2) {
            uint32_t a = sB + swz((uint32_t)((wn + 8 * (j0 + bJ) + bR) * BKB + (kk + bK) * 2));
            asm volatile("ldmatrix.sync.aligned.m8n8.x4.shared.b16 {%0,%1,%2,%3}, [%4];"
                         : "=r"(bf[buf][j0][0]), "=r"(bf[buf][j0][1]),
                           "=r"(bf[buf][j0 + 1][0]), "=r"(bf[buf][j0 + 1][1]) : "r"(a));
        }
    };
    auto mmaStep = [&](int buf) {
#pragma unroll
        for (int i = 0; i < 4; ++i)
#pragma unroll
            for (int j = 0; j < 8; ++j)
                asm volatile(
                    "mma.sync.aligned.m16n8k16.row.col.f32.f16.f16.f32 "
                    "{%0,%1,%2,%3}, {%4,%5,%6,%7}, {%8,%9}, {%0,%1,%2,%3};"
                    : "+f"(acc[i][j][0]), "+f"(acc[i][j][1]),
                      "+f"(acc[i][j][2]), "+f"(acc[i][j][3])
                    : "r"(af[buf][i][0]), "r"(af[buf][i][1]), "r"(af[buf][i][2]), "r"(af[buf][i][3]),
                      "r"(bf[buf][j][0]), "r"(bf[buf][j][1]));
    };

    const int T = KD / 64;
    loadTile(0, 0); CP_COMMIT();
    loadTile(64, 1); CP_COMMIT();

    for (int tt = 0; tt < T; ++tt) {
        const int s = tt % 3;
        CP_WAIT(1);                         // stage tt resident
        __syncthreads();                    // all warps done reading stage (tt+2)%3
        if (tt + 2 < T) loadTile((tt + 2) * 64, (tt + 2) % 3);
        CP_COMMIT();                        // commit (possibly empty) to keep counts aligned

        ldFrags(0, s, 0);
#pragma unroll
        for (int kk = 0; kk < 4; ++kk) {
            if (kk < 3) ldFrags((kk + 1) & 1, s, (kk + 1) * 16);
            mmaStep(kk & 1);
        }
    }

    // ---- epilogue ----
#pragma unroll
    for (int i = 0; i < 4; ++i) {
        size_t r0 = rowBase + wm + 16 * i + g;
#pragma unroll
        for (int j = 0; j < 8; ++j) {
            int col = colBase + wn + 8 * j + 2 * t4;
            float b0 = bias[col], b1 = bias[col + 1];
#pragma unroll
            for (int rr = 0; rr < 2; ++rr) {
                size_t row = r0 + 8 * rr;
                float v0 = acc[i][j][2 * rr + 0] + b0;
                float v1 = acc[i][j][2 * rr + 1] + b1;
                if (GELU) {
                    v0 = 0.5f * v0 * (1.0f + erff(v0 * 0.70710678118654752f));
                    v1 = 0.5f * v1 * (1.0f + erff(v1 * 0.70710678118654752f));
                    *(__half2*)((__half*)outv + row * ND + col) = __floats2half2_rn(v0, v1);
                } else {
                    if (row < (size_t)Mreal)
                        *(float2*)((float*)outv + row * ND + col) = make_float2(v0, v1);
                }
            }
        }
    }
}

// ================= finalize: out0 = y0 ; out[c] = R @ y[1:4] =================
__global__ void finalize_kernel(const float* __restrict__ rot, float* __restrict__ out) {
    int n = blockIdx.x, f = threadIdx.x;
    __shared__ float R[9];
    if (f < 9) R[f] = rot[(size_t)n * 9 + f];
    __syncthreads();
    const float* y = g_y + (size_t)n * ODIMN;
    float y0 = y[f], y1 = y[128 + f], y2 = y[256 + f], y3 = y[384 + f];
    float* o = out + (size_t)n * ODIMN;
    o[f] = y0;
#pragma unroll
    for (int c = 0; c < 3; ++c)
        o[(c + 1) * 128 + f] = R[c * 3] * y1 + R[c * 3 + 1] * y2 + R[c * 3 + 2] * y3;
}

// ================= launch =================
extern "C" void kernel_launch(void* const* d_in, const int* in_sizes, int n_in,
                              void* d_out, int out_size) {
    const float* x     = (const float*)d_in[0];
    const float* rot   = (const float*)d_in[1];
    const float* extra = (const float*)d_in[2];
    const float* W1    = (const float*)d_in[3];
    const float* b1    = (const float*)d_in[4];
    const float* W2    = (const float*)d_in[5];
    const float* b2    = (const float*)d_in[6];
    float* out = (float*)d_out;

    const int Mreal  = in_sizes[0] / 512;           // 100000
    const int mTiles = (Mreal + 127) / 128;         // 782
    const int Mpad   = mTiles * 128;                // 100096

    void *px1, *ph, *py, *pw1, *pw2;
    cudaGetSymbolAddress(&px1, g_x1h);
    cudaGetSymbolAddress(&ph,  g_hh);
    cudaGetSymbolAddress(&py,  g_y);
    cudaGetSymbolAddress(&pw1, g_w1t);
    cudaGetSymbolAddress(&pw2, g_w2t);

    cudaFuncSetAttribute((gemm_h<K1, HIDN, 1>),    cudaFuncAttributeMaxDynamicSharedMemorySize, SMEMB);
    cudaFuncSetAttribute((gemm_h<HIDN, ODIMN, 0>), cudaFuncAttributeMaxDynamicSharedMemorySize, SMEMB);

    // weights -> transposed half (W1 with matching k-permutation)
    {
        long n1 = (long)HIDN * K1;
        wprep_kernel<1><<<(unsigned)((n1 + 255) / 256), 256>>>(W1, (__half*)pw1, K1, HIDN);
        long n2 = (long)ODIMN * HIDN;
        wprep_kernel<0><<<(unsigned)((n2 + 255) / 256), 256>>>(W2, (__half*)pw2, HIDN, ODIMN);
    }
    // x1 (padded rows zeroed)
    prep_kernel<<<Mpad, 128>>>(x, rot, extra, Mreal);

    // GEMM1: h = gelu(x1 @ W1 + b1)  (half out)
    {
        dim3 grid(HIDN / 256, mTiles);
        gemm_h<K1, HIDN, 1><<<grid, 256, SMEMB>>>((const __half*)px1, (const __half*)pw1,
                                                  b1, ph, Mreal);
    }
    // GEMM2: y = h @ W2 + b2  (fp32 out)
    {
        dim3 grid(ODIMN / 256, mTiles);
        gemm_h<HIDN, ODIMN, 0><<<grid, 256, SMEMB>>>((const __half*)ph, (const __half*)pw2,
                                                     b2, py, Mreal);
    }
    finalize_kernel<<<Mreal, 128>>>(rot, out);
}

// round 7
// speedup vs baseline: 1.0946x; 1.0946x over previous
#include <cuda_runtime.h>
#include <cuda_fp16.h>
#include <math.h>
#include <stdint.h>

// ================= problem constants =================
#define MCAP   100096              // 782*128 padded row capacity
#define K1     1152
#define HIDN   1024
#define ODIMN  512

// ================= scratch (device globals; allocation-free rule) =================
__device__ __half g_x1h[(size_t)MCAP * K1];     // x1, half, row-major, permuted cols
__device__ __half g_hh [(size_t)MCAP * HIDN];   // h,  half, row-major
__device__ float  g_y  [(size_t)MCAP * ODIMN];  // y,  fp32, row-major
__device__ __half g_w1t[(size_t)HIDN * K1];     // W1^T [N][K], permuted rows
__device__ __half g_w2t[(size_t)ODIMN * HIDN];  // W2^T [N][K]

// ================= helpers =================
__device__ __forceinline__ uint32_t smem_u32(const void* p) {
    uint32_t a;
    asm("{ .reg .u64 t; cvta.to.shared.u64 t, %1; cvt.u32.u64 %0, t; }" : "=r"(a) : "l"(p));
    return a;
}
// XOR swizzle: 16B chunk (bits 4-6) ^ row%8 (bits 7-9); rows are 128B
__device__ __forceinline__ uint32_t swz(uint32_t b) { return b ^ ((b >> 3) & 0x70); }

__device__ __forceinline__ void cpa16(uint32_t dst, const void* src) {
    asm volatile("cp.async.cg.shared.global [%0], [%1], 16;" :: "r"(dst), "l"(src) : "memory");
}
#define CP_COMMIT() asm volatile("cp.async.commit_group;" ::: "memory")
#define CP_WAIT(n)  asm volatile("cp.async.wait_group %0;" :: "n"(n) : "memory")

// ================= prep: x1 (half, permuted cols, padded rows zeroed) =================
// col order: [x0(128) | vl_j0(128) | vl_j1(128) | vl_j2(128) | norm(128) | extra(512)]
__global__ void prep_kernel(const float* __restrict__ x, const float* __restrict__ rot,
                            const float* __restrict__ extra, int Mreal) {
    int n = blockIdx.x, f = threadIdx.x;
    bool real = n < Mreal;
    __shared__ float R[9];
    if (real && f < 9) R[f] = rot[(size_t)n * 9 + f];
    __syncthreads();

    float x0 = 0.f, v1 = 0.f, v2 = 0.f, v3 = 0.f;
    if (real) {
        const float* xr = x + (size_t)n * 512;
        x0 = xr[f]; v1 = xr[128 + f]; v2 = xr[256 + f]; v3 = xr[384 + f];
    }
    __half* o = g_x1h + (size_t)n * K1;
    o[f] = __float2half(x0);
#pragma unroll
    for (int j = 0; j < 3; ++j) {
        float vl = real ? (v1 * R[j] + v2 * R[3 + j] + v3 * R[6 + j]) : 0.f;
        o[128 + 128 * j + f] = __float2half(vl);
    }
    o[512 + f] = __float2half(real ? sqrtf(v1 * v1 + v2 * v2 + v3 * v3 + 1e-4f) : 0.f);
#pragma unroll
    for (int j = 0; j < 4; ++j) {
        float e = real ? extra[(size_t)n * 512 + 128 * j + f] : 0.f;
        o[640 + 128 * j + f] = __float2half(e);
    }
}

// ================= weight prep: W[K][N] fp32 -> W^T[N][K] half (PERM row remap for W1) ======
template<int PERM>
__global__ void wprep_kernel(const float* __restrict__ W, __half* __restrict__ dst, int K, int N) {
    long t = (long)blockIdx.x * blockDim.x + threadIdx.x;
    if (t >= (long)N * K) return;
    int n = (int)(t / K), k = (int)(t % K);
    int nk = k;
    if (PERM && k >= 128 && k < 512) {
        int q = k - 128;
        nk = 128 + (q % 3) * 128 + (q / 3);
    }
    dst[(size_t)n * K + nk] = __float2half(W[(size_t)k * N + n]);
}

// ================= fp16 tensor-core GEMM =================
// C[M,ND] = A[M,KD] @ B^T (B stored [ND][KD] half).
// CTA tile 128x128x64, 256 thr = 8 warps (2x4), warp tile 64x32, 2 CTAs/SM.
// mma.m16n8k16, x4 ldmatrix for A and B, 3-stage cp.async, ONE sync per K-tile.
#define BKB   128                      // K-tile bytes per row (64 halfs)
#define STAGE 32768                    // 16KB A + 16KB B
#define SMEMB (3 * STAGE)              // 98304 (<=113KB -> 2 CTAs/SM)

template<int KD, int ND, int GELU>
__global__ void __launch_bounds__(256, 2)
gemm_h(const __half* __restrict__ A, const __half* __restrict__ B,
       const float* __restrict__ bias, void* __restrict__ outv, int Mreal) {
    extern __shared__ char smem[];
    const uint32_t sbase = smem_u32(smem);

    const int tid = threadIdx.x, lane = tid & 31;
    const int warp = tid >> 5;
    const int wm = (warp >> 2) * 64;         // warp row offset (0,64)
    const int wn = (warp & 3) * 32;          // warp col offset (0..96)
    const int g = lane >> 2, t4 = lane & 3;
    const size_t rowBase = (size_t)blockIdx.y * 128;
    const int colBase = blockIdx.x * 128;

    // ldmatrix lane address components (proven in R4/R6)
    const int aR = (lane & 7) + ((lane >> 3) & 1) * 8;   // A: row within m16
    const int aK = (lane >> 4) * 8;                      // A: k-half
    const int bR = lane & 7;                             // B: row within n8
    const int bJ = (lane >> 4) & 1;                      // B: j sub-block (x4 spans 2 n8s)
    const int bK = ((lane >> 3) & 1) * 8;                // B: k-half

    float acc[4][4][4];
#pragma unroll
    for (int i = 0; i < 4; ++i)
#pragma unroll
        for (int j = 0; j < 4; ++j)
#pragma unroll
            for (int r = 0; r < 4; ++r) acc[i][j][r] = 0.0f;

    auto loadTile = [&](int k0, int s) {
        const uint32_t sA = sbase + s * STAGE;
        const uint32_t sB = sA + 16384;
#pragma unroll
        for (int p = 0; p < 4; ++p) {                 // A: 1024 16B chunks
            int idx = tid + p * 256;
            int r = idx >> 3, c = idx & 7;
            cpa16(sA + swz((uint32_t)(r * BKB + c * 16)),
                  A + (rowBase + r) * KD + k0 + c * 8);
        }
#pragma unroll
        for (int p = 0; p < 4; ++p) {                 // B: 1024 16B chunks
            int idx = tid + p * 256;
            int r = idx >> 3, c = idx & 7;
            cpa16(sB + swz((uint32_t)(r * BKB + c * 16)),
                  B + (size_t)(colBase + r) * KD + k0 + c * 8);
        }
    };

    const int T = KD / 64;
    loadTile(0, 0); CP_COMMIT();
    loadTile(64, 1); CP_COMMIT();

    for (int tt = 0; tt < T; ++tt) {
        const int s = tt % 3;
        const uint32_t sA = sbase + s * STAGE;
        const uint32_t sB = sA + 16384;

        CP_WAIT(1);                         // stage tt resident
        __syncthreads();                    // all warps done reading stage (tt+2)%3
        if (tt + 2 < T) loadTile((tt + 2) * 64, (tt + 2) % 3);
        CP_COMMIT();                        // (possibly empty) keeps group counts aligned

#pragma unroll
        for (int kk = 0; kk < 64; kk += 16) {
            uint32_t af[4][4], bf[4][2];
#pragma unroll
            for (int i = 0; i < 4; ++i) {
                uint32_t a = sA + swz((uint32_t)((wm + 16 * i + aR) * BKB + (kk + aK) * 2));
                asm volatile("ldmatrix.sync.aligned.m8n8.x4.shared.b16 {%0,%1,%2,%3}, [%4];"
                             : "=r"(af[i][0]), "=r"(af[i][1]), "=r"(af[i][2]), "=r"(af[i][3]) : "r"(a));
            }
#pragma unroll
            for (int j0 = 0; j0 < 4; j0 += 2) {
                uint32_t a = sB + swz((uint32_t)((wn + 8 * (j0 + bJ) + bR) * BKB + (kk + bK) * 2));
                asm volatile("ldmatrix.sync.aligned.m8n8.x4.shared.b16 {%0,%1,%2,%3}, [%4];"
                             : "=r"(bf[j0][0]), "=r"(bf[j0][1]),
                               "=r"(bf[j0 + 1][0]), "=r"(bf[j0 + 1][1]) : "r"(a));
            }
#pragma unroll
            for (int i = 0; i < 4; ++i)
#pragma unroll
                for (int j = 0; j < 4; ++j)
                    asm volatile(
                        "mma.sync.aligned.m16n8k16.row.col.f32.f16.f16.f32 "
                        "{%0,%1,%2,%3}, {%4,%5,%6,%7}, {%8,%9}, {%0,%1,%2,%3};"
                        : "+f"(acc[i][j][0]), "+f"(acc[i][j][1]),
                          "+f"(acc[i][j][2]), "+f"(acc[i][j][3])
                        : "r"(af[i][0]), "r"(af[i][1]), "r"(af[i][2]), "r"(af[i][3]),
                          "r"(bf[j][0]), "r"(bf[j][1]));
        }
    }

    // ---- epilogue ----
#pragma unroll
    for (int i = 0; i < 4; ++i) {
        size_t r0 = rowBase + wm + 16 * i + g;
#pragma unroll
        for (int j = 0; j < 4; ++j) {
            int col = colBase + wn + 8 * j + 2 * t4;
            float b0 = bias[col], b1 = bias[col + 1];
#pragma unroll
            for (int rr = 0; rr < 2; ++rr) {
                size_t row = r0 + 8 * rr;
                float v0 = acc[i][j][2 * rr + 0] + b0;
                float v1 = acc[i][j][2 * rr + 1] + b1;
                if (GELU) {
                    v0 = 0.5f * v0 * (1.0f + erff(v0 * 0.70710678118654752f));
                    v1 = 0.5f * v1 * (1.0f + erff(v1 * 0.70710678118654752f));
                    *(__half2*)((__half*)outv + row * ND + col) = __floats2half2_rn(v0, v1);
                } else {
                    if (row < (size_t)Mreal)
                        *(float2*)((float*)outv + row * ND + col) = make_float2(v0, v1);
                }
            }
        }
    }
}

// ================= finalize: out0 = y0 ; out[c] = R @ y[1:4] =================
__global__ void finalize_kernel(const float* __restrict__ rot, float* __restrict__ out) {
    int n = blockIdx.x, f = threadIdx.x;
    __shared__ float R[9];
    if (f < 9) R[f] = rot[(size_t)n * 9 + f];
    __syncthreads();
    const float* y = g_y + (size_t)n * ODIMN;
    float y0 = y[f], y1 = y[128 + f], y2 = y[256 + f], y3 = y[384 + f];
    float* o = out + (size_t)n * ODIMN;
    o[f] = y0;
#pragma unroll
    for (int c = 0; c < 3; ++c)
        o[(c + 1) * 128 + f] = R[c * 3] * y1 + R[c * 3 + 1] * y2 + R[c * 3 + 2] * y3;
}

// ================= launch =================
extern "C" void kernel_launch(void* const* d_in, const int* in_sizes, int n_in,
                              void* d_out, int out_size) {
    const float* x     = (const float*)d_in[0];
    const float* rot   = (const float*)d_in[1];
    const float* extra = (const float*)d_in[2];
    const float* W1    = (const float*)d_in[3];
    const float* b1    = (const float*)d_in[4];
    const float* W2    = (const float*)d_in[5];
    const float* b2    = (const float*)d_in[6];
    float* out = (float*)d_out;

    const int Mreal  = in_sizes[0] / 512;           // 100000
    const int mTiles = (Mreal + 127) / 128;         // 782
    const int Mpad   = mTiles * 128;                // 100096

    void *px1, *ph, *py, *pw1, *pw2;
    cudaGetSymbolAddress(&px1, g_x1h);
    cudaGetSymbolAddress(&ph,  g_hh);
    cudaGetSymbolAddress(&py,  g_y);
    cudaGetSymbolAddress(&pw1, g_w1t);
    cudaGetSymbolAddress(&pw2, g_w2t);

    cudaFuncSetAttribute((gemm_h<K1, HIDN, 1>),    cudaFuncAttributeMaxDynamicSharedMemorySize, SMEMB);
    cudaFuncSetAttribute((gemm_h<HIDN, ODIMN, 0>), cudaFuncAttributeMaxDynamicSharedMemorySize, SMEMB);

    // weights -> transposed half (W1 with matching k-permutation)
    {
        long n1 = (long)HIDN * K1;
        wprep_kernel<1><<<(unsigned)((n1 + 255) / 256), 256>>>(W1, (__half*)pw1, K1, HIDN);
        long n2 = (long)ODIMN * HIDN;
        wprep_kernel<0><<<(unsigned)((n2 + 255) / 256), 256>>>(W2, (__half*)pw2, HIDN, ODIMN);
    }
    // x1 (padded rows zeroed)
    prep_kernel<<<Mpad, 128>>>(x, rot, extra, Mreal);

    // GEMM1: h = gelu(x1 @ W1 + b1)  (half out)
    {
        dim3 grid(HIDN / 128, mTiles);
        gemm_h<K1, HIDN, 1><<<grid, 256, SMEMB>>>((const __half*)px1, (const __half*)pw1,
                                                  b1, ph, Mreal);
    }
    // GEMM2: y = h @ W2 + b2  (fp32 out)
    {
        dim3 grid(ODIMN / 128, mTiles);
        gemm_h<HIDN, ODIMN, 0><<<grid, 256, SMEMB>>>((const __half*)ph, (const __half*)pw2,
                                                     b2, py, Mreal);
    }
    finalize_kernel<<<Mreal, 128>>>(rot, out);
}